// round 11
// baseline (speedup 1.0000x reference)
#include <cuda_runtime.h>

#define BATCH 256
#define TT    512
#define NN    128
#define SEG   32
#define NCK   (TT / SEG)   // 16 checkpoints

__global__ __launch_bounds__(256)
void viterbi_kernel(const float* __restrict__ logits,
                    const float* __restrict__ trans,
                    const int*   __restrict__ lens,
                    float*       __restrict__ out) {   // OUTPUT AS FLOAT32
    __shared__ __align__(16) float sb[2][NN];        // ping-pong Viterbi state
    __shared__ __align__(16) float ck[NCK][NN];      // checkpoints (t = 32*s)
    __shared__ unsigned char bps[SEG][NN];           // per-segment backpointers
    __shared__ int s_cur;

    const int tid = threadIdx.x;
    const int j   = tid >> 1;     // tag owned by this thread pair
    const int h   = tid & 1;      // half of i-range: [64h, 64h+64)
    const int b   = blockIdx.x;   // one block per batch

    const float* xb    = logits + (size_t)b * TT * NN;
    const size_t obase = (size_t)b * TT;
    int L = __ldg(lens + b);
    L = max(1, min(L, TT));       // defensive clamp (no-op on valid data)

    // Per-thread transition registers: tr[rr] = T[64h + rr][j].
    float tr[64];
    #pragma unroll
    for (int rr = 0; rr < 64; ++rr)
        tr[rr] = __ldg(trans + (size_t)(64 * h + rr) * NN + j);

    // init: state0 = logits[b,0,:]; zero output row (mask for t >= L).
    if (h == 0) {
        float v = __ldg(xb + j);
        sb[0][j] = v;
        ck[0][j] = v;
    }
    out[obase + tid]       = 0.0f;
    out[obase + tid + 256] = 0.0f;
    __syncthreads();

    const float NEG_INF = __int_as_float(0xff800000);

    // ---------------- forward (values only) with checkpoints ----------------
    int pp = 0;
    float xcur = __ldg(xb + NN + j);                                   // x[1][j]
    for (int t = 1; t < L; ++t) {
        float xnext = __ldg(xb + (size_t)min(t + 1, TT - 1) * NN + j); // prefetch

        const float4* s4 = (const float4*)(&sb[pp][0]) + (h << 4);
        float m0 = NEG_INF, m1 = NEG_INF, m2 = NEG_INF, m3 = NEG_INF;
        #pragma unroll
        for (int g = 0; g < 16; ++g) {
            float4 s = s4[g];
            m0 = fmaxf(m0, s.x + tr[4 * g + 0]);
            m1 = fmaxf(m1, s.y + tr[4 * g + 1]);
            m2 = fmaxf(m2, s.z + tr[4 * g + 2]);
            m3 = fmaxf(m3, s.w + tr[4 * g + 3]);
        }
        float mf = fmaxf(fmaxf(m0, m1), fmaxf(m2, m3));
        mf = fmaxf(mf, __shfl_xor_sync(0xffffffffu, mf, 1));

        if (h == 0) {
            float ns = mf + xcur;
            sb[pp ^ 1][j] = ns;
            if ((t & (SEG - 1)) == 0) ck[t >> 5][j] = ns;  // state_{32s}
        }
        xcur = xnext;
        __syncthreads();
        pp ^= 1;
    }

    // ---------------- last_tag: serial first-index argmax ----------------
    if (tid == 0) {
        const float* fs = &sb[pp][0];
        float m = fs[0];
        int  bi = 0;
        for (int i = 1; i < NN; ++i) {
            float v = fs[i];
            if (v > m) { m = v; bi = i; }
        }
        out[obase + (L - 1)] = (float)bi;
        s_cur = bi;
    }
    __syncthreads();

    // ---------------- backtrace: recompute 32-step segments ----------------
    // Recomputed sums state[i]+T[i][j] are bitwise identical to the forward
    // pass, so first-index argmax reproduces the reference backpointers.
    if (L >= 2) {
        for (int s = (L - 2) / SEG; s >= 0; --s) {
            const int t0 = s * SEG + 1;
            const int t1 = min(s * SEG + SEG, L - 1);

            if (h == 0) sb[0][j] = ck[s][j];   // state at t0-1
            __syncthreads();

            int qq = 0;
            float xc = __ldg(xb + (size_t)t0 * NN + j);
            for (int t = t0; t <= t1; ++t) {
                float xn = __ldg(xb + (size_t)min(t + 1, TT - 1) * NN + j);

                const float4* s4 = (const float4*)(&sb[qq][0]) + (h << 4);
                float m  = NEG_INF;
                int   bi = 64 * h;
                #pragma unroll
                for (int g = 0; g < 16; ++g) {
                    float4 sv = s4[g];
                    float v0 = sv.x + tr[4 * g + 0];
                    if (v0 > m) { m = v0; bi = 64 * h + 4 * g + 0; }
                    float v1 = sv.y + tr[4 * g + 1];
                    if (v1 > m) { m = v1; bi = 64 * h + 4 * g + 1; }
                    float v2 = sv.z + tr[4 * g + 2];
                    if (v2 > m) { m = v2; bi = 64 * h + 4 * g + 2; }
                    float v3 = sv.w + tr[4 * g + 3];
                    if (v3 > m) { m = v3; bi = 64 * h + 4 * g + 3; }
                }
                float mo  = __shfl_xor_sync(0xffffffffu, m, 1);
                int   bio = __shfl_xor_sync(0xffffffffu, bi, 1);
                if (mo > m || (mo == m && bio < bi)) { m = mo; bi = bio; }

                if (h == 0) {
                    bps[t - t0][j] = (unsigned char)bi;
                    sb[qq ^ 1][j]  = m + xc;
                }
                xc = xn;
                __syncthreads();
                qq ^= 1;
            }

            if (tid == 0) {
                int cur = s_cur;
                for (int t = t1; t >= t0; --t) {
                    cur = bps[t - t0][cur];
                    out[obase + (t - 1)] = (float)cur;
                }
                s_cur = cur;
            }
            __syncthreads();
        }
    }
}

extern "C" void kernel_launch(void* const* d_in, const int* in_sizes, int n_in,
                              void* d_out, int out_size) {
    // Fixed-order defaults (logits, transitions, sequence_lengths), overridden
    // by size matching in ELEMENTS or BYTES. Never nullptr.
    const float* logits = (const float*)d_in[0];
    const float* trans  = (const float*)((n_in > 1) ? d_in[1] : d_in[0]);
    const int*   lens   = (const int*)((n_in > 2) ? d_in[2] : d_in[0]);
    for (int i = 0; i < n_in; ++i) {
        int s = in_sizes[i];
        if      (s == BATCH * TT * NN || s == BATCH * TT * NN * 4) logits = (const float*)d_in[i];
        else if (s == NN * NN         || s == NN * NN * 4)         trans  = (const float*)d_in[i];
        else if (s == BATCH           || s == BATCH * 4)           lens   = (const int*)d_in[i];
    }
    float* out = (float*)d_out;
    (void)out_size;

    viterbi_kernel<<<BATCH, 256>>>(logits, trans, lens, out);
}

// round 13
// speedup vs baseline: 3.1559x; 3.1559x over previous
#include <cuda_runtime.h>

#define BATCH 256
#define TT    512
#define NN    128

// 64 MiB state history + batch ordering (static __device__ = allocation-free).
__device__ __align__(16) float d_hist[(size_t)BATCH * TT * NN];
__device__ int d_order[BATCH];

// Rank-sort batches by length descending (unique ranks via index tie-break).
__global__ void sort_kernel(const int* __restrict__ lens) {
    int b = threadIdx.x;
    int L = lens[b];
    int r = 0;
    for (int k = 0; k < BATCH; ++k) {
        int Lk = lens[k];
        r += (Lk > L) || (Lk == L && k < b);
    }
    d_order[r] = b;
}

// Order-preserving f32 -> u32 map (finite inputs).
__device__ __forceinline__ unsigned ordf(float f) {
    int b = __float_as_int(f);
    return (unsigned)(b ^ ((b >> 31) | 0x80000000));
}

__global__ __launch_bounds__(256)
void viterbi_kernel(const float* __restrict__ logits,
                    const float* __restrict__ trans,
                    const int*   __restrict__ lens,
                    float*       __restrict__ out) {   // output dtype: float32
    extern __shared__ float smem[];
    float* transT = smem;              // [NN][NN]: transT[j*NN+i] = T[i][j] (64KB)
    float* sb     = transT + NN * NN;  // [2][NN] ping-pong state

    const int tid  = threadIdx.x;
    const int j    = tid >> 1;         // tag owned by this thread pair
    const int h    = tid & 1;          // half of i-range: [64h, 64h+64)
    const int lane = tid & 31;

    // Length-balanced pairing: rank m with rank 255-m (bijective over 0..255).
    const int bk   = blockIdx.x;
    const int rank = (bk < 148) ? bk : (403 - bk);
    const int b    = d_order[rank];

    int L = __ldg(lens + b);
    L = max(1, min(L, TT));            // defensive clamp (no-op on valid data)

    const float* xb    = logits + (size_t)b * TT * NN;
    float*       hb    = d_hist + (size_t)b * TT * NN;
    const size_t obase = (size_t)b * TT;

    // Fill transposed transitions in smem (one-time).
    for (int k = tid; k < NN * NN; k += 256) {
        int i = k >> 7, jj = k & 127;
        transT[jj * NN + i] = __ldg(trans + k);
    }

    // Per-thread transition registers: tr[r] = T[64h + r][j].
    float tr[64];
    #pragma unroll
    for (int r = 0; r < 64; ++r)
        tr[r] = __ldg(trans + (size_t)(64 * h + r) * NN + j);

    // init: state0 = logits[b,0,:]; zero output row (mask for t >= L).
    if (h == 0) {
        float v = __ldg(xb + j);
        sb[j] = v;
        hb[j] = v;
    }
    out[obase + tid]       = 0.0f;
    out[obase + tid + 256] = 0.0f;
    __syncthreads();

    const float NEG_INF = __int_as_float(0xff800000);

    // ---------------- forward (values only) + history store ----------------
    int pp = 0;
    float xcur = __ldg(xb + NN + j);                                   // x[1][j]
    for (int t = 1; t < L; ++t) {
        float xnext = __ldg(xb + (size_t)min(t + 1, TT - 1) * NN + j); // prefetch

        const float4* s4 = (const float4*)(sb + pp * NN) + (h << 4);
        float m0 = NEG_INF, m1 = NEG_INF, m2 = NEG_INF, m3 = NEG_INF;
        #pragma unroll
        for (int g = 0; g < 16; ++g) {
            float4 s = s4[g];
            m0 = fmaxf(m0, s.x + tr[4 * g + 0]);
            m1 = fmaxf(m1, s.y + tr[4 * g + 1]);
            m2 = fmaxf(m2, s.z + tr[4 * g + 2]);
            m3 = fmaxf(m3, s.w + tr[4 * g + 3]);
        }
        float mf = fmaxf(fmaxf(m0, m1), fmaxf(m2, m3));
        mf = fmaxf(mf, __shfl_xor_sync(0xffffffffu, mf, 1));

        if (h == 0) {
            float ns = mf + xcur;
            sb[(pp ^ 1) * NN + j] = ns;
            hb[(size_t)t * NN + j] = ns;
        }
        xcur = xnext;
        __syncthreads();
        pp ^= 1;
    }

    // ---------------- backtrace by single-column recompute (warp 0) ----------------
    // Recomputed sums state_{t-1}[i] + T[i][cur] are bitwise identical to the
    // forward pass, so first-index argmax reproduces the reference backpointers.
    if (tid < 32) {
        // last_tag = first-index argmax of final state.
        const float4 sv = ((const float4*)(sb + pp * NN))[lane];
        float lm = sv.x; int li = 0;
        if (sv.y > lm) { lm = sv.y; li = 1; }
        if (sv.z > lm) { lm = sv.z; li = 2; }
        if (sv.w > lm) { lm = sv.w; li = 3; }
        unsigned uu   = ordf(lm);
        unsigned Mg   = __reduce_max_sync(0xffffffffu, uu);
        unsigned cand = (uu == Mg) ? (unsigned)(4 * lane + li) : 0xffffffffu;
        int cur = (int)__reduce_min_sync(0xffffffffu, cand);
        if (lane == 0) out[obase + (L - 1)] = (float)cur;

        // Depth-2 prefetch of history rows (addresses independent of cur).
        float4 rA = ((const float4*)(hb + (size_t)max(L - 2, 0) * NN))[lane];
        float4 rB = ((const float4*)(hb + (size_t)max(L - 3, 0) * NN))[lane];

        for (int t = L - 1; t >= 1; --t) {
            float4 r = rA;                         // state_{t-1}
            rA = rB;
            rB = ((const float4*)(hb + (size_t)max(t - 3, 0) * NN))[lane];

            // T[:, cur] from smem transposed copy: only cur-dependent access is LDS.
            const float4 tv = ((const float4*)(transT + cur * NN))[lane];
            float v0 = r.x + tv.x, v1 = r.y + tv.y;
            float v2 = r.z + tv.z, v3 = r.w + tv.w;
            float lm2 = v0; int li2 = 0;
            if (v1 > lm2) { lm2 = v1; li2 = 1; }
            if (v2 > lm2) { lm2 = v2; li2 = 2; }
            if (v3 > lm2) { lm2 = v3; li2 = 3; }
            unsigned u2 = ordf(lm2);
            unsigned M2 = __reduce_max_sync(0xffffffffu, u2);
            unsigned c2 = (u2 == M2) ? (unsigned)(4 * lane + li2) : 0xffffffffu;
            cur = (int)__reduce_min_sync(0xffffffffu, c2);
            if (lane == 0) out[obase + (t - 1)] = (float)cur;
        }
    }
}

extern "C" void kernel_launch(void* const* d_in, const int* in_sizes, int n_in,
                              void* d_out, int out_size) {
    const float* logits = (const float*)d_in[0];
    const float* trans  = (const float*)((n_in > 1) ? d_in[1] : d_in[0]);
    const int*   lens   = (const int*)((n_in > 2) ? d_in[2] : d_in[0]);
    for (int i = 0; i < n_in; ++i) {
        int s = in_sizes[i];
        if      (s == BATCH * TT * NN) logits = (const float*)d_in[i];
        else if (s == NN * NN)         trans  = (const float*)d_in[i];
        else if (s == BATCH)           lens   = (const int*)d_in[i];
    }
    float* out = (float*)d_out;
    (void)out_size;

    const int smem_bytes = (NN * NN + 2 * NN) * (int)sizeof(float);  // 65.5 KB
    cudaFuncSetAttribute(viterbi_kernel,
                         cudaFuncAttributeMaxDynamicSharedMemorySize, smem_bytes);

    sort_kernel<<<1, BATCH>>>(lens);
    viterbi_kernel<<<BATCH, 256, smem_bytes>>>(logits, trans, lens, out);
}